// round 3
// baseline (speedup 1.0000x reference)
#include <cuda_runtime.h>
#include <cuda_bf16.h>
#include <math.h>

#define D_MODEL 1024
#define N_HEADS 16
#define HEAD_DIM 64
#define KV_DIM 256
#define SEQ_T 2048
#define BATCH 2
#define ROWS (BATCH * SEQ_T)   // 4096

// ---------------- scratch (device globals; no allocation allowed) -----------
__device__ float g_kv[ROWS * KV_DIM];     // 4 MB
__device__ float g_q [ROWS * D_MODEL];    // 16 MB
__device__ float g_k [ROWS * D_MODEL];    // 16 MB
__device__ float g_v [ROWS * D_MODEL];    // 16 MB
__device__ float g_y [ROWS * D_MODEL];    // 16 MB

// ---------------- SGEMM: C = A[MxK] @ B[KxN] + bias, all row-major ----------
__global__ __launch_bounds__(256) void sgemm_bias(
    const float* __restrict__ A, const float* __restrict__ B,
    const float* __restrict__ bias, float* __restrict__ C,
    int M, int N, int K)
{
    __shared__ float As[8][128];
    __shared__ float Bs[8][128];
    const int tid = threadIdx.x;
    const int bm = blockIdx.y * 128;
    const int bn = blockIdx.x * 128;

    const int a_row = tid >> 1;          // 0..127
    const int a_col = (tid & 1) * 4;     // 0 or 4
    const int b_row = tid >> 5;          // 0..7
    const int b_col = (tid & 31) * 4;    // 0..124
    const int tr = tid >> 4;             // 0..15
    const int tc = tid & 15;             // 0..15

    float acc[8][8];
    #pragma unroll
    for (int i = 0; i < 8; i++)
        #pragma unroll
        for (int j = 0; j < 8; j++) acc[i][j] = 0.f;

    const float* Aptr = A + (size_t)(bm + a_row) * K + a_col;
    const float* Bptr = B + (size_t)b_row * N + bn + b_col;

    for (int k0 = 0; k0 < K; k0 += 8) {
        float4 av = *(const float4*)(Aptr + k0);
        float4 bv = *(const float4*)(Bptr + (size_t)k0 * N);
        As[a_col + 0][a_row] = av.x;
        As[a_col + 1][a_row] = av.y;
        As[a_col + 2][a_row] = av.z;
        As[a_col + 3][a_row] = av.w;
        *(float4*)&Bs[b_row][b_col] = bv;
        __syncthreads();
        #pragma unroll
        for (int k = 0; k < 8; k++) {
            float ra[8], rb[8];
            #pragma unroll
            for (int i = 0; i < 8; i++) ra[i] = As[k][tr * 8 + i];
            #pragma unroll
            for (int j = 0; j < 8; j++) rb[j] = Bs[k][tc * 8 + j];
            #pragma unroll
            for (int i = 0; i < 8; i++)
                #pragma unroll
                for (int j = 0; j < 8; j++) acc[i][j] += ra[i] * rb[j];
        }
        __syncthreads();
    }

    #pragma unroll
    for (int i = 0; i < 8; i++) {
        int row = bm + tr * 8 + i;
        #pragma unroll
        for (int j = 0; j < 8; j++) {
            int col = bn + tc * 8 + j;
            C[(size_t)row * N + col] = acc[i][j] + bias[col];
        }
    }
}

// ---------------- RoPE on q (in-place). Layout [ROWS, H*64] -----------------
__global__ void rope_q_kernel(float* __restrict__ q)
{
    int idx = blockIdx.x * blockDim.x + threadIdx.x;   // ROWS*16*32 threads
    if (idx >= ROWS * N_HEADS * 32) return;
    int d   = idx & 31;
    int h   = (idx >> 5) & 15;
    int row = idx >> 9;
    int t   = row & (SEQ_T - 1);
    float inv = powf(10000.0f, -(float)d / 32.0f);
    float ang = (float)t * inv;
    float s, c;
    sincosf(ang, &s, &c);
    float* p = q + (size_t)row * D_MODEL + h * HEAD_DIM + d;
    float q1 = p[0], q2 = p[32];
    p[0]  = q1 * c - q2 * s;
    p[32] = q2 * c + q1 * s;
}

// ------------- k' = (k * t) @ Wkr per (row, head). In-place. ----------------
#define KT_PAIRS 16
__global__ __launch_bounds__(256) void k_transform_kernel(
    float* __restrict__ k, const float* __restrict__ Wkr)
{
    __shared__ float w[64 * 64];
    __shared__ float kin[KT_PAIRS][64];
    const int tid = threadIdx.x;
    const int pair0 = blockIdx.x * KT_PAIRS;    // pair = row*16 + h

    for (int i = tid; i < 4096; i += 256) w[i] = Wkr[i];
    for (int i = tid; i < KT_PAIRS * 64; i += 256) {
        int p   = pair0 + (i >> 6);
        int row = p >> 4, h = p & 15;
        float tpos = (float)(row & (SEQ_T - 1));
        kin[i >> 6][i & 63] = k[(size_t)row * D_MODEL + h * HEAD_DIM + (i & 63)] * tpos;
    }
    __syncthreads();

    const int o0 = tid * 4;
    const int p  = o0 >> 6;        // local pair (4 outputs stay in one pair)
    const int j0 = o0 & 63;
    float out[4] = {0.f, 0.f, 0.f, 0.f};
    #pragma unroll 8
    for (int i = 0; i < 64; i++) {
        float kv_ = kin[p][i];
        #pragma unroll
        for (int c = 0; c < 4; c++) out[c] += kv_ * w[i * 64 + j0 + c];
    }
    int gp = pair0 + p;
    int row = gp >> 4, h = gp & 15;
    #pragma unroll
    for (int c = 0; c < 4; c++)
        k[(size_t)row * D_MODEL + h * HEAD_DIM + j0 + c] = out[c];
}

// ---------------- flash attention (fp32), causal, 64x64 tiles ---------------
// grid: (T/64, H, B); 256 threads as 16x16, each thread a 4x4 microtile.
__global__ __launch_bounds__(256) void flash_attn_kernel(
    const float* __restrict__ q, const float* __restrict__ k,
    const float* __restrict__ v, float* __restrict__ y)
{
    extern __shared__ float sm[];
    float* Qs = sm;                 // [64][64]
    float* Ks = sm + 4096;          // [64][65]  (also reused as P)
    float* Vs = Ks + 64 * 65;       // [64][64]

    const int tid = threadIdx.x;
    const int ty = tid >> 4, tx = tid & 15;
    const int it = blockIdx.x;
    const int h  = blockIdx.y;
    const int b  = blockIdx.z;
    const int qbase = it * 64;

    const float* qp = q + ((size_t)(b * SEQ_T + qbase)) * D_MODEL + h * HEAD_DIM;
    for (int i = tid; i < 4096; i += 256)
        Qs[i] = qp[(size_t)(i >> 6) * D_MODEL + (i & 63)];

    float m_[4], l_[4], O[4][4];
    #pragma unroll
    for (int r = 0; r < 4; r++) {
        m_[r] = -1e30f; l_[r] = 0.f;
        #pragma unroll
        for (int c = 0; c < 4; c++) O[r][c] = 0.f;
    }

    for (int jt = 0; jt <= it; jt++) {
        const int kbase = jt * 64;
        const float* kp = k + ((size_t)(b * SEQ_T + kbase)) * D_MODEL + h * HEAD_DIM;
        const float* vp = v + ((size_t)(b * SEQ_T + kbase)) * D_MODEL + h * HEAD_DIM;
        __syncthreads();   // prev iter done with Ks/Vs (and first iter: Qs ready)
        for (int i = tid; i < 4096; i += 256) {
            int rr = i >> 6, cc = i & 63;
            Ks[rr * 65 + cc] = kp[(size_t)rr * D_MODEL + cc];
            Vs[i]            = vp[(size_t)rr * D_MODEL + cc];
        }
        __syncthreads();

        // S = Q @ K^T
        float S[4][4];
        #pragma unroll
        for (int r = 0; r < 4; r++)
            #pragma unroll
            for (int c = 0; c < 4; c++) S[r][c] = 0.f;
        #pragma unroll 4
        for (int d = 0; d < 64; d++) {
            float ra[4], rb[4];
            #pragma unroll
            for (int r = 0; r < 4; r++) ra[r] = Qs[(ty * 4 + r) * 64 + d];
            #pragma unroll
            for (int c = 0; c < 4; c++) rb[c] = Ks[(tx * 4 + c) * 65 + d];
            #pragma unroll
            for (int r = 0; r < 4; r++)
                #pragma unroll
                for (int c = 0; c < 4; c++) S[r][c] += ra[r] * rb[c];
        }

        const float scale = 0.125f;    // 1/sqrt(64)
        const bool diag = (jt == it);
        float corr[4];
        #pragma unroll
        for (int r = 0; r < 4; r++) {
            #pragma unroll
            for (int c = 0; c < 4; c++) {
                float s_ = S[r][c] * scale;
                if (diag && (tx * 4 + c) > (ty * 4 + r)) s_ = -1e30f;
                S[r][c] = s_;
            }
            float mx = fmaxf(fmaxf(S[r][0], S[r][1]), fmaxf(S[r][2], S[r][3]));
            #pragma unroll
            for (int off = 8; off; off >>= 1)
                mx = fmaxf(mx, __shfl_xor_sync(0xffffffffu, mx, off, 16));
            float mnew = fmaxf(m_[r], mx);
            corr[r] = __expf(m_[r] - mnew);
            m_[r] = mnew;
            float rs = 0.f;
            #pragma unroll
            for (int c = 0; c < 4; c++) {
                float p_ = __expf(S[r][c] - mnew);
                S[r][c] = p_;
                rs += p_;
            }
            #pragma unroll
            for (int off = 8; off; off >>= 1)
                rs += __shfl_xor_sync(0xffffffffu, rs, off, 16);
            l_[r] = l_[r] * corr[r] + rs;
            #pragma unroll
            for (int c = 0; c < 4; c++) O[r][c] *= corr[r];
        }

        // write P into Ks buffer, then O += P @ V
        __syncthreads();
        #pragma unroll
        for (int r = 0; r < 4; r++)
            #pragma unroll
            for (int c = 0; c < 4; c++)
                Ks[(ty * 4 + r) * 65 + tx * 4 + c] = S[r][c];
        __syncthreads();
        #pragma unroll 4
        for (int s = 0; s < 64; s++) {
            float ra[4];
            #pragma unroll
            for (int r = 0; r < 4; r++) ra[r] = Ks[(ty * 4 + r) * 65 + s];
            float4 bv = *(float4*)&Vs[s * 64 + tx * 4];
            float rb[4] = {bv.x, bv.y, bv.z, bv.w};
            #pragma unroll
            for (int r = 0; r < 4; r++)
                #pragma unroll
                for (int c = 0; c < 4; c++) O[r][c] += ra[r] * rb[c];
        }
    }

    float* yp = y + ((size_t)(b * SEQ_T + qbase)) * D_MODEL + h * HEAD_DIM;
    #pragma unroll
    for (int r = 0; r < 4; r++) {
        float inv = 1.0f / l_[r];
        #pragma unroll
        for (int c = 0; c < 4; c++)
            yp[(size_t)(ty * 4 + r) * D_MODEL + tx * 4 + c] = O[r][c] * inv;
    }
}

// ---------------------------------------------------------------------------
extern "C" void kernel_launch(void* const* d_in, const int* in_sizes, int n_in,
                              void* d_out, int out_size)
{
    const float* x   = (const float*)d_in[0];
    // d_in[1] = mask (causal, known statically — ignored)
    const float* Wq  = (const float*)d_in[2];
    const float* bq  = (const float*)d_in[3];
    const float* Wkv = (const float*)d_in[4];
    const float* bkv = (const float*)d_in[5];
    const float* Wk  = (const float*)d_in[6];
    const float* bk  = (const float*)d_in[7];
    const float* Wv  = (const float*)d_in[8];
    const float* bv  = (const float*)d_in[9];
    const float* Wo  = (const float*)d_in[10];
    const float* bo  = (const float*)d_in[11];
    const float* Wkr = (const float*)d_in[12];
    float* out = (float*)d_out;

    float *kv, *q, *k, *v, *y;
    cudaGetSymbolAddress((void**)&kv, g_kv);
    cudaGetSymbolAddress((void**)&q,  g_q);
    cudaGetSymbolAddress((void**)&k,  g_k);
    cudaGetSymbolAddress((void**)&v,  g_v);
    cudaGetSymbolAddress((void**)&y,  g_y);

    const int fa_smem = (4096 + 64 * 65 + 4096) * (int)sizeof(float);   // 49408
    cudaFuncSetAttribute(flash_attn_kernel,
                         cudaFuncAttributeMaxDynamicSharedMemorySize, fa_smem);

    // kv = x @ Wkv + bkv
    sgemm_bias<<<dim3(KV_DIM / 128, ROWS / 128), 256>>>(x, Wkv, bkv, kv, ROWS, KV_DIM, D_MODEL);
    // q = x @ Wq + bq
    sgemm_bias<<<dim3(D_MODEL / 128, ROWS / 128), 256>>>(x, Wq, bq, q, ROWS, D_MODEL, D_MODEL);
    // k = kv @ Wk + bk ; v = kv @ Wv + bv
    sgemm_bias<<<dim3(D_MODEL / 128, ROWS / 128), 256>>>(kv, Wk, bk, k, ROWS, D_MODEL, KV_DIM);
    sgemm_bias<<<dim3(D_MODEL / 128, ROWS / 128), 256>>>(kv, Wv, bv, v, ROWS, D_MODEL, KV_DIM);
    // RoPE(q)
    rope_q_kernel<<<(ROWS * N_HEADS * 32) / 256, 256>>>(q);
    // k = (k * t) @ Wkr per head
    k_transform_kernel<<<(ROWS * N_HEADS) / KT_PAIRS, 256>>>(k, Wkr);
    // y = softmax(q k^T / 8, causal) @ v
    flash_attn_kernel<<<dim3(SEQ_T / 64, N_HEADS, BATCH), 256, fa_smem>>>(q, k, v, y);
    // out = y @ Wo + bo
    sgemm_bias<<<dim3(D_MODEL / 128, ROWS / 128), 256>>>(y, Wo, bo, out, ROWS, D_MODEL, D_MODEL);
}